// round 2
// baseline (speedup 1.0000x reference)
#include <cuda_runtime.h>

#define N_NODES 50000
#define N_EDGES 800000
#define IN_DIM  128
#define OUT_DIM 64
#define NUM_HEADS 4

// Scratch (static device globals — no allocation allowed in kernel_launch)
__device__ float4 g_hp4[N_NODES * (OUT_DIM / 4)];          // projected features, 12.8 MB
__device__ float  g_wavg[IN_DIM * OUT_DIM];                // mean-over-heads weight, 32 KB

// ---------------------------------------------------------------------------
// Kernel 1: W_avg[d][f] = (1/4) * sum_k W[k][d][f]
// ---------------------------------------------------------------------------
__global__ void k_wavg(const float* __restrict__ W) {
    int i = blockIdx.x * blockDim.x + threadIdx.x;   // 0 .. 8191
    if (i < IN_DIM * OUT_DIM) {
        float s = W[i] + W[IN_DIM * OUT_DIM + i]
                + W[2 * IN_DIM * OUT_DIM + i] + W[3 * IN_DIM * OUT_DIM + i];
        g_wavg[i] = 0.25f * s;
    }
}

// ---------------------------------------------------------------------------
// Kernel 2: zero the output accumulator (harness poisons d_out)
// ---------------------------------------------------------------------------
__global__ void k_zero(float4* __restrict__ out4) {
    int i = blockIdx.x * blockDim.x + threadIdx.x;   // 0 .. 800000-1
    if (i < N_NODES * (OUT_DIM / 4))
        out4[i] = make_float4(0.f, 0.f, 0.f, 0.f);
}

// ---------------------------------------------------------------------------
// Kernel 3: hp = h @ W_avg        [50000 x 128] x [128 x 64]
// 256 threads/block, 256 rows/block. Thread = (row-slot rs, col-group cg):
// computes 4 consecutive rows x 16 consecutive cols (64 accumulators).
// W_avg staged in 32 KB smem; h read as float4 straight from global (L1/L2).
// ---------------------------------------------------------------------------
__global__ void __launch_bounds__(256, 2) k_gemm(const float4* __restrict__ h4) {
    __shared__ float4 sW[(IN_DIM * OUT_DIM) / 4];    // 2048 float4 = 32 KB
    int tid = threadIdx.x;
    const float4* wsrc = (const float4*)g_wavg;
    #pragma unroll
    for (int i = 0; i < 8; ++i)
        sW[tid + 256 * i] = wsrc[tid + 256 * i];
    __syncthreads();

    int cg = tid & 3;            // column group: cols [cg*16, cg*16+16)
    int rs = tid >> 2;           // row slot 0..63
    int r0 = blockIdx.x * 256 + rs * 4;

    float acc[4][16];
    #pragma unroll
    for (int i = 0; i < 4; ++i)
        #pragma unroll
        for (int c = 0; c < 16; ++c) acc[i][c] = 0.f;

    const float4 z4 = make_float4(0.f, 0.f, 0.f, 0.f);

    for (int d4 = 0; d4 < IN_DIM / 4; ++d4) {
        float4 ha[4];
        #pragma unroll
        for (int i = 0; i < 4; ++i) {
            int r = r0 + i;
            ha[i] = (r < N_NODES) ? h4[r * (IN_DIM / 4) + d4] : z4;
        }
        #pragma unroll
        for (int j = 0; j < 4; ++j) {
            int d = d4 * 4 + j;
            float4 w0 = sW[d * 16 + cg * 4 + 0];
            float4 w1 = sW[d * 16 + cg * 4 + 1];
            float4 w2 = sW[d * 16 + cg * 4 + 2];
            float4 w3 = sW[d * 16 + cg * 4 + 3];
            #pragma unroll
            for (int i = 0; i < 4; ++i) {
                float hv = (j == 0) ? ha[i].x : (j == 1) ? ha[i].y
                         : (j == 2) ? ha[i].z : ha[i].w;
                acc[i][0]  += hv * w0.x; acc[i][1]  += hv * w0.y;
                acc[i][2]  += hv * w0.z; acc[i][3]  += hv * w0.w;
                acc[i][4]  += hv * w1.x; acc[i][5]  += hv * w1.y;
                acc[i][6]  += hv * w1.z; acc[i][7]  += hv * w1.w;
                acc[i][8]  += hv * w2.x; acc[i][9]  += hv * w2.y;
                acc[i][10] += hv * w2.z; acc[i][11] += hv * w2.w;
                acc[i][12] += hv * w3.x; acc[i][13] += hv * w3.y;
                acc[i][14] += hv * w3.z; acc[i][15] += hv * w3.w;
            }
        }
    }

    #pragma unroll
    for (int i = 0; i < 4; ++i) {
        int r = r0 + i;
        if (r < N_NODES) {
            #pragma unroll
            for (int k = 0; k < 4; ++k) {
                g_hp4[r * 16 + cg * 4 + k] =
                    make_float4(acc[i][k * 4 + 0], acc[i][k * 4 + 1],
                                acc[i][k * 4 + 2], acc[i][k * 4 + 3]);
            }
        }
    }
}

// ---------------------------------------------------------------------------
// Kernel 4: scatter-sum.  16 threads per edge; each thread moves one float4
// via vector reduction (red.global.add.v4.f32, sm_90+) — 4x fewer L2 atomic
// ops than scalar atomicAdd, no return trip.
// ---------------------------------------------------------------------------
__global__ void k_scatter(const int* __restrict__ src, const int* __restrict__ dst,
                          float* __restrict__ out) {
    int g = blockIdx.x * blockDim.x + threadIdx.x;
    int e = g >> 4;
    int q = g & 15;
    if (e >= N_EDGES) return;
    int s = __ldg(src + e);
    int d = __ldg(dst + e);
    float4 v = g_hp4[s * 16 + q];          // contiguous 256B per edge across 16 lanes
    float* p = out + d * OUT_DIM + q * 4;  // 16B-aligned
    asm volatile("red.global.add.v4.f32 [%0], {%1, %2, %3, %4};"
                 :: "l"(p), "f"(v.x), "f"(v.y), "f"(v.z), "f"(v.w)
                 : "memory");
}

// ---------------------------------------------------------------------------
// Kernel 5: out = relu(out + b)
// ---------------------------------------------------------------------------
__global__ void k_epi(float4* __restrict__ out4, const float4* __restrict__ b4) {
    int i = blockIdx.x * blockDim.x + threadIdx.x;
    if (i >= N_NODES * (OUT_DIM / 4)) return;
    float4 v  = out4[i];
    float4 bb = b4[i & 15];
    v.x = fmaxf(v.x + bb.x, 0.f);
    v.y = fmaxf(v.y + bb.y, 0.f);
    v.z = fmaxf(v.z + bb.z, 0.f);
    v.w = fmaxf(v.w + bb.w, 0.f);
    out4[i] = v;
}

// ---------------------------------------------------------------------------
extern "C" void kernel_launch(void* const* d_in, const int* in_sizes, int n_in,
                              void* d_out, int out_size) {
    const float* h   = (const float*)d_in[0];
    const float* W   = (const float*)d_in[1];
    const float* b   = (const float*)d_in[2];
    const int*   src = (const int*)d_in[3];
    const int*   dst = (const int*)d_in[4];
    float*       out = (float*)d_out;

    k_wavg<<<(IN_DIM * OUT_DIM + 255) / 256, 256>>>(W);
    k_zero<<<(N_NODES * (OUT_DIM / 4) + 255) / 256, 256>>>((float4*)out);
    k_gemm<<<(N_NODES + 255) / 256, 256>>>((const float4*)h);
    k_scatter<<<(N_EDGES * 16) / 256, 256>>>(src, dst, out);
    k_epi<<<(N_NODES * (OUT_DIM / 4) + 255) / 256, 256>>>((float4*)out, (const float4*)b);
}